// round 1
// baseline (speedup 1.0000x reference)
#include <cuda_runtime.h>
#include <cuda_bf16.h>

#define NN 50000
#define EE 800000
#define GG 256
#define FMAX 128

// ---------------- device scratch (static, no allocation) ----------------
__device__ float  g_deg[NN];
__device__ float  g_dis[NN];
__device__ int    g_count[NN];
__device__ int    g_fill[NN];
__device__ int    g_rowptr[NN + 1];
__device__ int    g_blocksum[64];
__device__ int    g_blockoff[64];
__device__ int    g_src[EE];
__device__ float  g_wn[EE];
__device__ float  g_bufA[NN * FMAX];
__device__ float  g_bufB[NN * FMAX];
__device__ float  g_m[NN * FMAX];
__device__ double g_sum[FMAX];
__device__ double g_sq[FMAX];
__device__ float  g_scale[FMAX];
__device__ float  g_shift[FMAX];
__device__ float  g_pooled[GG * FMAX];

// ---------------- preprocessing ----------------
__global__ void init_kernel() {
    int i = blockIdx.x * blockDim.x + threadIdx.x;
    if (i < NN) { g_deg[i] = 1.0f; g_count[i] = 0; g_fill[i] = 0; }
    if (i < GG * FMAX) g_pooled[i] = 0.0f;
}

__global__ void count_kernel(const int* __restrict__ ei, const float* __restrict__ ew) {
    int e = blockIdx.x * blockDim.x + threadIdx.x;
    if (e < EE) {
        int c = ei[EE + e];
        atomicAdd(&g_deg[c], ew[e]);
        atomicAdd(&g_count[c], 1);
    }
}

__global__ void dis_kernel() {
    int i = blockIdx.x * blockDim.x + threadIdx.x;
    if (i < NN) g_dis[i] = rsqrtf(g_deg[i]);  // deg >= 1 always (self loop)
}

__global__ void scan1_kernel() {
    __shared__ int s[1024];
    int t = threadIdx.x;
    int i = blockIdx.x * 1024 + t;
    int v = (i < NN) ? g_count[i] : 0;
    s[t] = v;
    __syncthreads();
    #pragma unroll
    for (int off = 1; off < 1024; off <<= 1) {
        int x = (t >= off) ? s[t - off] : 0;
        __syncthreads();
        s[t] += x;
        __syncthreads();
    }
    if (i < NN) g_rowptr[i + 1] = s[t];
    if (t == 1023) g_blocksum[blockIdx.x] = s[1023];
    if (i == 0) g_rowptr[0] = 0;
}

__global__ void scan2_kernel() {
    __shared__ int s[64];
    int t = threadIdx.x;
    const int nb = (NN + 1023) / 1024;
    int v = (t < nb) ? g_blocksum[t] : 0;
    s[t] = v;
    __syncthreads();
    #pragma unroll
    for (int off = 1; off < 64; off <<= 1) {
        int x = (t >= off) ? s[t - off] : 0;
        __syncthreads();
        s[t] += x;
        __syncthreads();
    }
    g_blockoff[t] = s[t] - v;  // exclusive
}

__global__ void scan3_kernel() {
    int i = blockIdx.x * blockDim.x + threadIdx.x;
    if (i < NN) g_rowptr[i + 1] += g_blockoff[i / 1024];
}

__global__ void scatter_kernel(const int* __restrict__ ei, const float* __restrict__ ew) {
    int e = blockIdx.x * blockDim.x + threadIdx.x;
    if (e < EE) {
        int r = ei[e];
        int c = ei[EE + e];
        int pos = g_rowptr[c] + atomicAdd(&g_fill[c], 1);
        g_src[pos] = r;
        g_wn[pos]  = g_dis[r] * ew[e] * g_dis[c];
    }
}

__global__ void zero_stats_kernel() {
    int i = threadIdx.x;
    if (i < FMAX) { g_sum[i] = 0.0; g_sq[i] = 0.0; }
}

// ---------------- dense transform: m = h @ W ----------------
template <int DIN, int DOUT>
__global__ __launch_bounds__(256)
void matmul_kernel(const float* __restrict__ h, const float* __restrict__ W,
                   float* __restrict__ out) {
    constexpr int TILE = 32;
    constexpr int VECW = (DOUT >= 32) ? 4 : 2;
    constexpr int CG   = DOUT / VECW;
    constexpr int RG   = 256 / CG;
    constexpr int RPT  = TILE / RG;
    __shared__ __align__(16) float sW[DIN * DOUT];
    __shared__ __align__(16) float sH[TILE * DIN];
    int t = threadIdx.x;
    int node0 = blockIdx.x * TILE;
    for (int i = t; i < DIN * DOUT; i += 256) sW[i] = W[i];
    for (int i = t; i < TILE * DIN; i += 256) {
        int nn = node0 + i / DIN;
        sH[i] = (nn < NN) ? h[nn * DIN + i % DIN] : 0.0f;
    }
    __syncthreads();
    int cg = t % CG, rg = t / CG;
    float acc[RPT][VECW];
    #pragma unroll
    for (int r = 0; r < RPT; r++)
        #pragma unroll
        for (int v = 0; v < VECW; v++) acc[r][v] = 0.0f;
    #pragma unroll 4
    for (int k = 0; k < DIN; k++) {
        float wv[VECW];
        #pragma unroll
        for (int v = 0; v < VECW; v++) wv[v] = sW[k * DOUT + cg * VECW + v];
        #pragma unroll
        for (int r = 0; r < RPT; r++) {
            float hv = sH[(rg * RPT + r) * DIN + k];
            #pragma unroll
            for (int v = 0; v < VECW; v++) acc[r][v] += hv * wv[v];
        }
    }
    #pragma unroll
    for (int r = 0; r < RPT; r++) {
        int node = node0 + rg * RPT + r;
        if (node < NN) {
            #pragma unroll
            for (int v = 0; v < VECW; v++)
                out[node * DOUT + cg * VECW + v] = acc[r][v];
        }
    }
}

// ---------------- gather aggregation + bias (+relu) + BN partial stats ----------------
template <int DOUT, bool RELU>
__global__ __launch_bounds__(256)
void aggregate_kernel(const float* __restrict__ m, const float* __restrict__ b,
                      float* __restrict__ out) {
    constexpr int NT  = (DOUT < 32) ? DOUT : 32;
    constexpr int VEC = DOUT / NT;
    constexpr int NPB = 256 / NT;
    __shared__ float s_sum[DOUT];
    __shared__ float s_sq[DOUT];
    int tid = threadIdx.x;
    for (int i = tid; i < DOUT; i += 256) { s_sum[i] = 0.0f; s_sq[i] = 0.0f; }
    __syncthreads();
    int lane = tid % NT;
    int node = blockIdx.x * NPB + tid / NT;
    if (node < NN) {
        float acc[VEC];
        float dn = g_dis[node];
        float sn = dn * dn;  // self-loop norm
        #pragma unroll
        for (int v = 0; v < VEC; v++) acc[v] = b[lane * VEC + v];
        // self-loop contribution
        if constexpr (VEC == 4) {
            float4 mv = __ldg(reinterpret_cast<const float4*>(m) + node * (DOUT / 4) + lane);
            acc[0] += sn * mv.x; acc[1] += sn * mv.y; acc[2] += sn * mv.z; acc[3] += sn * mv.w;
        } else if constexpr (VEC == 2) {
            float2 mv = __ldg(reinterpret_cast<const float2*>(m) + node * (DOUT / 2) + lane);
            acc[0] += sn * mv.x; acc[1] += sn * mv.y;
        } else {
            acc[0] += sn * __ldg(m + node * DOUT + lane);
        }
        int e0 = g_rowptr[node], e1 = g_rowptr[node + 1];
        for (int e = e0; e < e1; e++) {
            int   s = __ldg(&g_src[e]);
            float w = __ldg(&g_wn[e]);
            if constexpr (VEC == 4) {
                float4 mv = __ldg(reinterpret_cast<const float4*>(m) + s * (DOUT / 4) + lane);
                acc[0] += w * mv.x; acc[1] += w * mv.y; acc[2] += w * mv.z; acc[3] += w * mv.w;
            } else if constexpr (VEC == 2) {
                float2 mv = __ldg(reinterpret_cast<const float2*>(m) + s * (DOUT / 2) + lane);
                acc[0] += w * mv.x; acc[1] += w * mv.y;
            } else {
                acc[0] += w * __ldg(m + s * DOUT + lane);
            }
        }
        #pragma unroll
        for (int v = 0; v < VEC; v++) {
            float val = acc[v];
            if (RELU) val = fmaxf(val, 0.0f);
            out[node * DOUT + lane * VEC + v] = val;
            atomicAdd(&s_sum[lane * VEC + v], val);
            atomicAdd(&s_sq[lane * VEC + v], val * val);
        }
    }
    __syncthreads();
    for (int i = tid; i < DOUT; i += 256) {
        atomicAdd(&g_sum[i], (double)s_sum[i]);
        atomicAdd(&g_sq[i],  (double)s_sq[i]);
    }
}

// ---------------- BN: stats -> scale/shift ----------------
__global__ void bn_stats_kernel(const float* __restrict__ g, const float* __restrict__ bt,
                                int dout) {
    int i = threadIdx.x;
    if (i < dout) {
        double mu  = g_sum[i] / (double)NN;
        double var = g_sq[i] / (double)NN - mu * mu;
        if (var < 0.0) var = 0.0;
        double sc = (double)g[i] * rsqrt(var + 1e-5);
        g_scale[i] = (float)sc;
        g_shift[i] = (float)((double)bt[i] - mu * sc);
    }
}

// ---------------- BN apply (+relu) (+pool) ----------------
template <int DOUT, bool RELU, bool POOL>
__global__ __launch_bounds__(256)
void bn_apply_kernel(float* __restrict__ h, const int* __restrict__ batch) {
    int i = blockIdx.x * blockDim.x + threadIdx.x;
    if (i >= NN * DOUT) return;
    int c    = i % DOUT;
    int node = i / DOUT;
    float v = g_scale[c] * h[i] + g_shift[c];
    if (RELU) v = fmaxf(v, 0.0f);
    h[i] = v;
    if (POOL) atomicAdd(&g_pooled[batch[node] * DOUT + c], v);
}

// ---------------- final MLP over G graphs ----------------
__global__ void mlp_kernel(const float* __restrict__ fc1_w, const float* __restrict__ fc1_b,
                           const float* __restrict__ fc2_w, const float* __restrict__ fc2_b,
                           float* __restrict__ out) {
    int g = blockIdx.x;
    int t = threadIdx.x;  // 64 threads
    __shared__ float sp[FMAX];
    for (int i = t; i < FMAX; i += 64) sp[i] = fmaxf(g_pooled[g * FMAX + i], 0.0f);
    __syncthreads();
    float acc = fc1_b[t];
    #pragma unroll 4
    for (int k = 0; k < FMAX; k++) acc += sp[k] * fc1_w[k * 64 + t];
    acc = fmaxf(acc, 0.0f);
    float v = acc * fc2_w[t];
    #pragma unroll
    for (int off = 16; off > 0; off >>= 1) v += __shfl_down_sync(0xffffffffu, v, off);
    __shared__ float red[2];
    if ((t & 31) == 0) red[t >> 5] = v;
    __syncthreads();
    if (t == 0) out[g] = red[0] + red[1] + fc2_b[0];
}

// ---------------- launch ----------------
extern "C" void kernel_launch(void* const* d_in, const int* in_sizes, int n_in,
                              void* d_out, int out_size) {
    const float* x     = (const float*)d_in[0];
    const int*   ei    = (const int*)d_in[1];
    const float* ew    = (const float*)d_in[2];
    const int*   batch = (const int*)d_in[3];
    const float *W1 = (const float*)d_in[4],  *b1 = (const float*)d_in[5],
                *g1 = (const float*)d_in[6],  *bt1 = (const float*)d_in[7];
    const float *W2 = (const float*)d_in[8],  *b2 = (const float*)d_in[9],
                *g2 = (const float*)d_in[10], *bt2 = (const float*)d_in[11];
    const float *W3 = (const float*)d_in[12], *b3 = (const float*)d_in[13],
                *g3 = (const float*)d_in[14], *bt3 = (const float*)d_in[15];
    const float *W4 = (const float*)d_in[16], *b4 = (const float*)d_in[17],
                *g4 = (const float*)d_in[18], *bt4 = (const float*)d_in[19];
    const float *W5 = (const float*)d_in[20], *b5 = (const float*)d_in[21],
                *g5 = (const float*)d_in[22], *bt5 = (const float*)d_in[23];
    const float* fc1_w = (const float*)d_in[24];
    const float* fc1_b = (const float*)d_in[25];
    const float* fc2_w = (const float*)d_in[26];
    const float* fc2_b = (const float*)d_in[27];
    float* out = (float*)d_out;

    float *bufA, *bufB, *bufM;
    cudaGetSymbolAddress((void**)&bufA, g_bufA);
    cudaGetSymbolAddress((void**)&bufB, g_bufB);
    cudaGetSymbolAddress((void**)&bufM, g_m);

    const int TB = 256;
    // preprocessing: degree -> dis -> CSR
    init_kernel<<<(NN + TB - 1) / TB, TB>>>();
    count_kernel<<<(EE + TB - 1) / TB, TB>>>(ei, ew);
    dis_kernel<<<(NN + TB - 1) / TB, TB>>>();
    scan1_kernel<<<(NN + 1023) / 1024, 1024>>>();
    scan2_kernel<<<1, 64>>>();
    scan3_kernel<<<(NN + TB - 1) / TB, TB>>>();
    scatter_kernel<<<(EE + TB - 1) / TB, TB>>>(ei, ew);

    const int MM_BLOCKS = (NN + 31) / 32;

    // Layer 1: 128 -> 16, h = bn(relu(conv(x)))
    matmul_kernel<128, 16><<<MM_BLOCKS, 256>>>(x, W1, bufM);
    zero_stats_kernel<<<1, 128>>>();
    aggregate_kernel<16, true><<<(NN + 15) / 16, 256>>>(bufM, b1, bufA);
    bn_stats_kernel<<<1, 128>>>(g1, bt1, 16);
    bn_apply_kernel<16, false, false><<<(NN * 16 + TB - 1) / TB, TB>>>(bufA, batch);

    // Layer 2: 16 -> 32
    matmul_kernel<16, 32><<<MM_BLOCKS, 256>>>(bufA, W2, bufM);
    zero_stats_kernel<<<1, 128>>>();
    aggregate_kernel<32, true><<<(NN + 7) / 8, 256>>>(bufM, b2, bufB);
    bn_stats_kernel<<<1, 128>>>(g2, bt2, 32);
    bn_apply_kernel<32, false, false><<<(NN * 32 + TB - 1) / TB, TB>>>(bufB, batch);

    // Layer 3: 32 -> 64
    matmul_kernel<32, 64><<<MM_BLOCKS, 256>>>(bufB, W3, bufM);
    zero_stats_kernel<<<1, 128>>>();
    aggregate_kernel<64, true><<<(NN + 7) / 8, 256>>>(bufM, b3, bufA);
    bn_stats_kernel<<<1, 128>>>(g3, bt3, 64);
    bn_apply_kernel<64, false, false><<<(NN * 64 + TB - 1) / TB, TB>>>(bufA, batch);

    // Layer 4: 64 -> 64, h = relu(bn(conv))
    matmul_kernel<64, 64><<<MM_BLOCKS, 256>>>(bufA, W4, bufM);
    zero_stats_kernel<<<1, 128>>>();
    aggregate_kernel<64, false><<<(NN + 7) / 8, 256>>>(bufM, b4, bufB);
    bn_stats_kernel<<<1, 128>>>(g4, bt4, 64);
    bn_apply_kernel<64, true, false><<<(NN * 64 + TB - 1) / TB, TB>>>(bufB, batch);

    // Layer 5: 64 -> 128, h = bn(conv), then pool
    matmul_kernel<64, 128><<<MM_BLOCKS, 256>>>(bufB, W5, bufM);
    zero_stats_kernel<<<1, 128>>>();
    aggregate_kernel<128, false><<<(NN + 7) / 8, 256>>>(bufM, b5, bufA);
    bn_stats_kernel<<<1, 128>>>(g5, bt5, 128);
    bn_apply_kernel<128, false, true><<<(NN * 128 + TB - 1) / TB, TB>>>(bufA, batch);

    // MLP head
    mlp_kernel<<<GG, 64>>>(fc1_w, fc1_b, fc2_w, fc2_b, out);
}

// round 3
// speedup vs baseline: 1.3490x; 1.3490x over previous
#include <cuda_runtime.h>
#include <cuda_bf16.h>

#define NN 50000
#define EE 800000
#define GG 256
#define FMAX 128

// stat offsets per layer: L1=0(16ch) L2=128(32) L3=256(64) L4=384(64) L5=512(128)
__device__ float  g_deg[NN];
__device__ float  g_dis[NN];
__device__ int    g_count[NN];
__device__ int    g_fill[NN];
__device__ int    g_rowptr[NN + 1];
__device__ int    g_blocksum[64];
__device__ int    g_blockoff[64];
__device__ int    g_src[EE];
__device__ float  g_wn[EE];
__device__ float  g_bufA[NN * FMAX];
__device__ float  g_m[NN * FMAX];
__device__ double g_sum[640];
__device__ double g_sq[640];
__device__ float  g_pooled[GG * FMAX];

// ---------------- preprocessing ----------------
__global__ void init_kernel() {
    int i = blockIdx.x * blockDim.x + threadIdx.x;
    if (i < NN) { g_deg[i] = 1.0f; g_count[i] = 0; g_fill[i] = 0; }
    if (i < GG * FMAX) g_pooled[i] = 0.0f;
    if (i < 640) { g_sum[i] = 0.0; g_sq[i] = 0.0; }
}

__global__ void count_kernel(const int* __restrict__ ei, const float* __restrict__ ew) {
    int e = blockIdx.x * blockDim.x + threadIdx.x;
    if (e < EE) {
        int c = ei[EE + e];
        atomicAdd(&g_deg[c], ew[e]);
        atomicAdd(&g_count[c], 1);
    }
}

__global__ void scan1_kernel() {
    __shared__ int s[1024];
    int t = threadIdx.x;
    int i = blockIdx.x * 1024 + t;
    int v = (i < NN) ? g_count[i] : 0;
    s[t] = v;
    if (i < NN) g_dis[i] = rsqrtf(g_deg[i]);  // deg >= 1 (self loop)
    __syncthreads();
    #pragma unroll
    for (int off = 1; off < 1024; off <<= 1) {
        int x = (t >= off) ? s[t - off] : 0;
        __syncthreads();
        s[t] += x;
        __syncthreads();
    }
    if (i < NN) g_rowptr[i + 1] = s[t];
    if (t == 1023) g_blocksum[blockIdx.x] = s[1023];
    if (i == 0) g_rowptr[0] = 0;
}

__global__ void scan2_kernel() {
    __shared__ int s[64];
    int t = threadIdx.x;
    const int nb = (NN + 1023) / 1024;
    int v = (t < nb) ? g_blocksum[t] : 0;
    s[t] = v;
    __syncthreads();
    #pragma unroll
    for (int off = 1; off < 64; off <<= 1) {
        int x = (t >= off) ? s[t - off] : 0;
        __syncthreads();
        s[t] += x;
        __syncthreads();
    }
    g_blockoff[t] = s[t] - v;
}

__global__ void scan3_kernel() {
    int i = blockIdx.x * blockDim.x + threadIdx.x;
    if (i < NN) g_rowptr[i + 1] += g_blockoff[i / 1024];
}

__global__ void scatter_kernel(const int* __restrict__ ei, const float* __restrict__ ew) {
    int e = blockIdx.x * blockDim.x + threadIdx.x;
    if (e < EE) {
        int r = ei[e];
        int c = ei[EE + e];
        int pos = g_rowptr[c] + atomicAdd(&g_fill[c], 1);
        g_src[pos] = r;
        g_wn[pos]  = g_dis[r] * ew[e] * g_dis[c];
    }
}

// ---------------- dense transform with fused BN-apply on input ----------------
// MODE: 0 = raw input, 1 = bn(h), 2 = relu(bn(h))
// dynamic smem layout: sW[DIN*DOUT] | sH[TILE*DIN] | sScale[DIN] | sShift[DIN]
template <int DIN, int DOUT, int MODE, int TILE>
__global__ __launch_bounds__(256)
void matmul_kernel(const float* __restrict__ h, const float* __restrict__ W,
                   float* __restrict__ out,
                   const float* __restrict__ gamma, const float* __restrict__ beta,
                   int stat_off) {
    constexpr int CG  = DOUT / 4;
    constexpr int RG  = 256 / CG;
    constexpr int RPT = TILE / RG;
    extern __shared__ float smem[];
    float* sW     = smem;
    float* sH     = smem + DIN * DOUT;
    float* sScale = sH + TILE * DIN;
    float* sShift = sScale + DIN;

    int t = threadIdx.x;
    if (MODE != 0 && t < DIN) {
        double mu  = g_sum[stat_off + t] / (double)NN;
        double var = g_sq[stat_off + t] / (double)NN - mu * mu;
        if (var < 0.0) var = 0.0;
        double sc = (double)gamma[t] * rsqrt(var + 1e-5);
        sScale[t] = (float)sc;
        sShift[t] = (float)((double)beta[t] - mu * sc);
    }
    for (int i = t; i < DIN * DOUT / 4; i += 256)
        ((float4*)sW)[i] = ((const float4*)W)[i];
    __syncthreads();

    int node0 = blockIdx.x * TILE;
    for (int i = t; i < TILE * DIN / 4; i += 256) {
        int nn = node0 + (i * 4) / DIN;
        int c  = (i * 4) % DIN;
        float4 v = make_float4(0.f, 0.f, 0.f, 0.f);
        if (nn < NN) v = ((const float4*)h)[nn * (DIN / 4) + c / 4];
        if (MODE != 0) {
            v.x = sScale[c + 0] * v.x + sShift[c + 0];
            v.y = sScale[c + 1] * v.y + sShift[c + 1];
            v.z = sScale[c + 2] * v.z + sShift[c + 2];
            v.w = sScale[c + 3] * v.w + sShift[c + 3];
            if (MODE == 2) {
                v.x = fmaxf(v.x, 0.f); v.y = fmaxf(v.y, 0.f);
                v.z = fmaxf(v.z, 0.f); v.w = fmaxf(v.w, 0.f);
            }
        }
        ((float4*)sH)[i] = v;
    }
    __syncthreads();

    int cg = t % CG, rg = t / CG;
    float acc[RPT][4];
    #pragma unroll
    for (int r = 0; r < RPT; r++) { acc[r][0]=0.f; acc[r][1]=0.f; acc[r][2]=0.f; acc[r][3]=0.f; }
    const float* sHr = sH + rg * RPT * DIN;
    #pragma unroll 8
    for (int k = 0; k < DIN; k++) {
        float4 wv = *(const float4*)(sW + k * DOUT + cg * 4);
        #pragma unroll
        for (int r = 0; r < RPT; r++) {
            float hv = sHr[r * DIN + k];
            acc[r][0] += hv * wv.x;
            acc[r][1] += hv * wv.y;
            acc[r][2] += hv * wv.z;
            acc[r][3] += hv * wv.w;
        }
    }
    #pragma unroll
    for (int r = 0; r < RPT; r++) {
        int node = node0 + rg * RPT + r;
        if (node < NN)
            ((float4*)out)[node * (DOUT / 4) + cg] =
                make_float4(acc[r][0], acc[r][1], acc[r][2], acc[r][3]);
    }
}

// ---------------- gather aggregation + bias (+relu) + BN stats ----------------
template <int DOUT, bool RELU>
__global__ __launch_bounds__(256)
void aggregate_kernel(const float* __restrict__ m, const float* __restrict__ b,
                      float* __restrict__ out, int stat_off) {
    constexpr int NT  = DOUT / 4;
    constexpr int NPB = 256 / NT;
    __shared__ float s_sum[DOUT];
    __shared__ float s_sq[DOUT];
    int tid = threadIdx.x;
    for (int i = tid; i < DOUT; i += 256) { s_sum[i] = 0.0f; s_sq[i] = 0.0f; }
    __syncthreads();
    int lane = tid % NT;
    int node = blockIdx.x * NPB + tid / NT;
    const float4* m4 = (const float4*)m;
    if (node < NN) {
        float dn = g_dis[node];
        float sn = dn * dn;
        float acc0 = b[lane * 4 + 0], acc1 = b[lane * 4 + 1];
        float acc2 = b[lane * 4 + 2], acc3 = b[lane * 4 + 3];
        float4 mv = __ldg(m4 + node * NT + lane);
        acc0 += sn * mv.x; acc1 += sn * mv.y; acc2 += sn * mv.z; acc3 += sn * mv.w;
        int e0 = g_rowptr[node], e1 = g_rowptr[node + 1];
        for (int e = e0; e < e1; e++) {
            int   s = __ldg(&g_src[e]);
            float w = __ldg(&g_wn[e]);
            float4 v = __ldg(m4 + s * NT + lane);
            acc0 += w * v.x; acc1 += w * v.y; acc2 += w * v.z; acc3 += w * v.w;
        }
        if (RELU) {
            acc0 = fmaxf(acc0, 0.f); acc1 = fmaxf(acc1, 0.f);
            acc2 = fmaxf(acc2, 0.f); acc3 = fmaxf(acc3, 0.f);
        }
        ((float4*)out)[node * NT + lane] = make_float4(acc0, acc1, acc2, acc3);
        atomicAdd(&s_sum[lane * 4 + 0], acc0); atomicAdd(&s_sq[lane * 4 + 0], acc0 * acc0);
        atomicAdd(&s_sum[lane * 4 + 1], acc1); atomicAdd(&s_sq[lane * 4 + 1], acc1 * acc1);
        atomicAdd(&s_sum[lane * 4 + 2], acc2); atomicAdd(&s_sq[lane * 4 + 2], acc2 * acc2);
        atomicAdd(&s_sum[lane * 4 + 3], acc3); atomicAdd(&s_sq[lane * 4 + 3], acc3 * acc3);
    }
    __syncthreads();
    for (int i = tid; i < DOUT; i += 256) {
        atomicAdd(&g_sum[stat_off + i], (double)s_sum[i]);
        atomicAdd(&g_sq[stat_off + i],  (double)s_sq[i]);
    }
}

// ---------------- layer5 BN + global_add_pool (batch is sorted) ----------------
__global__ __launch_bounds__(256)
void pool_kernel(const float* __restrict__ h, const int* __restrict__ batch,
                 const float* __restrict__ gamma, const float* __restrict__ beta) {
    __shared__ float sScale[128], sShift[128];
    int t = threadIdx.x;
    if (t < 128) {
        double mu  = g_sum[512 + t] / (double)NN;
        double var = g_sq[512 + t] / (double)NN - mu * mu;
        if (var < 0.0) var = 0.0;
        double sc = (double)gamma[t] * rsqrt(var + 1e-5);
        sScale[t] = (float)sc;
        sShift[t] = (float)((double)beta[t] - mu * sc);
    }
    __syncthreads();
    constexpr int NODES = 64;
    int lane = t % 32;
    int grp  = t / 32;  // 8 groups
    int base = blockIdx.x * NODES;
    float a0 = 0.f, a1 = 0.f, a2 = 0.f, a3 = 0.f;
    int cur = -1;
    float s0 = sScale[lane * 4 + 0], s1 = sScale[lane * 4 + 1];
    float s2 = sScale[lane * 4 + 2], s3 = sScale[lane * 4 + 3];
    float h0 = sShift[lane * 4 + 0], h1 = sShift[lane * 4 + 1];
    float h2 = sShift[lane * 4 + 2], h3 = sShift[lane * 4 + 3];
    for (int n = grp; n < NODES; n += 8) {
        int node = base + n;
        if (node >= NN) break;
        int bidx = batch[node];
        if (bidx != cur) {
            if (cur >= 0) {
                atomicAdd(&g_pooled[cur * 128 + lane * 4 + 0], a0);
                atomicAdd(&g_pooled[cur * 128 + lane * 4 + 1], a1);
                atomicAdd(&g_pooled[cur * 128 + lane * 4 + 2], a2);
                atomicAdd(&g_pooled[cur * 128 + lane * 4 + 3], a3);
            }
            cur = bidx; a0 = a1 = a2 = a3 = 0.f;
        }
        float4 v = ((const float4*)h)[node * 32 + lane];
        a0 += s0 * v.x + h0;
        a1 += s1 * v.y + h1;
        a2 += s2 * v.z + h2;
        a3 += s3 * v.w + h3;
    }
    if (cur >= 0) {
        atomicAdd(&g_pooled[cur * 128 + lane * 4 + 0], a0);
        atomicAdd(&g_pooled[cur * 128 + lane * 4 + 1], a1);
        atomicAdd(&g_pooled[cur * 128 + lane * 4 + 2], a2);
        atomicAdd(&g_pooled[cur * 128 + lane * 4 + 3], a3);
    }
}

// ---------------- final MLP over G graphs ----------------
__global__ void mlp_kernel(const float* __restrict__ fc1_w, const float* __restrict__ fc1_b,
                           const float* __restrict__ fc2_w, const float* __restrict__ fc2_b,
                           float* __restrict__ out) {
    int g = blockIdx.x;
    int t = threadIdx.x;  // 64
    __shared__ float sp[FMAX];
    for (int i = t; i < FMAX; i += 64) sp[i] = fmaxf(g_pooled[g * FMAX + i], 0.0f);
    __syncthreads();
    float acc = fc1_b[t];
    #pragma unroll 4
    for (int k = 0; k < FMAX; k++) acc += sp[k] * fc1_w[k * 64 + t];
    acc = fmaxf(acc, 0.0f);
    float v = acc * fc2_w[t];
    #pragma unroll
    for (int off = 16; off > 0; off >>= 1) v += __shfl_down_sync(0xffffffffu, v, off);
    __shared__ float red[2];
    if ((t & 31) == 0) red[t >> 5] = v;
    __syncthreads();
    if (t == 0) out[g] = red[0] + red[1] + fc2_b[0];
}

// ---------------- launch ----------------
extern "C" void kernel_launch(void* const* d_in, const int* in_sizes, int n_in,
                              void* d_out, int out_size) {
    const float* x     = (const float*)d_in[0];
    const int*   ei    = (const int*)d_in[1];
    const float* ew    = (const float*)d_in[2];
    const int*   batch = (const int*)d_in[3];
    const float *W1 = (const float*)d_in[4],  *b1 = (const float*)d_in[5],
                *g1 = (const float*)d_in[6],  *bt1 = (const float*)d_in[7];
    const float *W2 = (const float*)d_in[8],  *b2 = (const float*)d_in[9],
                *g2 = (const float*)d_in[10], *bt2 = (const float*)d_in[11];
    const float *W3 = (const float*)d_in[12], *b3 = (const float*)d_in[13],
                *g3 = (const float*)d_in[14], *bt3 = (const float*)d_in[15];
    const float *W4 = (const float*)d_in[16], *b4 = (const float*)d_in[17],
                *g4 = (const float*)d_in[18], *bt4 = (const float*)d_in[19];
    const float *W5 = (const float*)d_in[20], *b5 = (const float*)d_in[21],
                *g5 = (const float*)d_in[22], *bt5 = (const float*)d_in[23];
    const float* fc1_w = (const float*)d_in[24];
    const float* fc1_b = (const float*)d_in[25];
    const float* fc2_w = (const float*)d_in[26];
    const float* fc2_b = (const float*)d_in[27];
    float* out = (float*)d_out;

    float *bufA, *bufM;
    cudaGetSymbolAddress((void**)&bufA, g_bufA);
    cudaGetSymbolAddress((void**)&bufM, g_m);

    const int TB = 256;
    init_kernel<<<(NN + TB - 1) / TB, TB>>>();
    count_kernel<<<(EE + TB - 1) / TB, TB>>>(ei, ew);
    scan1_kernel<<<(NN + 1023) / 1024, 1024>>>();
    scan2_kernel<<<1, 64>>>();
    scan3_kernel<<<(NN + TB - 1) / TB, TB>>>();
    scatter_kernel<<<(EE + TB - 1) / TB, TB>>>(ei, ew);

    // dynamic smem bytes: (din*dout + tile*din + 2*din) * 4
    auto smem = [](int din, int dout, int tile) {
        return (din * dout + tile * din + 2 * din) * 4;
    };

    // L1: conv(x) -> relu -> stats   (TILE=64, 40.5KB)
    matmul_kernel<128, 16, 0, 64><<<(NN + 63) / 64, 256, smem(128, 16, 64)>>>(
        x, W1, bufM, nullptr, nullptr, 0);
    aggregate_kernel<16, true><<<(NN * 4 + 255) / 256, 256>>>(bufM, b1, bufA, 0);
    // L2: bn(h1) fused into input load
    matmul_kernel<16, 32, 1, 64><<<(NN + 63) / 64, 256, smem(16, 32, 64)>>>(
        bufA, W2, bufM, g1, bt1, 0);
    aggregate_kernel<32, true><<<(NN * 8 + 255) / 256, 256>>>(bufM, b2, bufA, 128);
    // L3
    matmul_kernel<32, 64, 1, 64><<<(NN + 63) / 64, 256, smem(32, 64, 64)>>>(
        bufA, W3, bufM, g2, bt2, 128);
    aggregate_kernel<64, true><<<(NN * 16 + 255) / 256, 256>>>(bufM, b3, bufA, 256);
    // L4: conv -> stats (no relu pre-BN)
    matmul_kernel<64, 64, 1, 64><<<(NN + 63) / 64, 256, smem(64, 64, 64)>>>(
        bufA, W4, bufM, g3, bt3, 256);
    aggregate_kernel<64, false><<<(NN * 16 + 255) / 256, 256>>>(bufM, b4, bufA, 384);
    // L5: input = relu(bn(h4))  (TILE=56 keeps smem at 46.5KB)
    matmul_kernel<64, 128, 2, 56><<<(NN + 55) / 56, 256, smem(64, 128, 56)>>>(
        bufA, W5, bufM, g4, bt4, 384);
    aggregate_kernel<128, false><<<(NN * 32 + 255) / 256, 256>>>(bufM, b5, bufA, 512);
    // BN(L5) + pool
    pool_kernel<<<(NN + 63) / 64, 256>>>(bufA, batch, g5, bt5);
    // MLP head
    mlp_kernel<<<GG, 64>>>(fc1_w, fc1_b, fc2_w, fc2_b, out);
}

// round 4
// speedup vs baseline: 1.9307x; 1.4312x over previous
#include <cuda_runtime.h>
#include <cuda_bf16.h>

#define NN 50000
#define EE 800000
#define GG 256
#define FMAX 128

// stat offsets: L1=0(16) L2=128(32) L3=256(64) L4=384(64) L5=512(128)
__device__ float  g_deg[NN];
__device__ float  g_dis[NN];
__device__ int    g_count[NN];
__device__ int    g_fill[NN];
__device__ int    g_rowptr[NN + 1];
__device__ int    g_blocksum[64];
__device__ int    g_blockoff[64];
__device__ int    g_src[EE];
__device__ float  g_wn[EE];
__device__ float  g_bufA[NN * FMAX];   // conv outputs / h_raw
__device__ float  g_bufB[NN * 64];     // pre-aggregated features (max 64 dims)
__device__ float  g_m[NN * 16];        // L1 matmul output
__device__ double g_sum[640];
__device__ double g_sq[640];
__device__ float  g_pooled[GG * FMAX];

// ---------------- preprocessing ----------------
__global__ void init_kernel() {
    int i = blockIdx.x * blockDim.x + threadIdx.x;
    if (i < NN) { g_deg[i] = 1.0f; g_count[i] = 0; g_fill[i] = 0; }
    if (i < GG * FMAX) g_pooled[i] = 0.0f;
    if (i < 640) { g_sum[i] = 0.0; g_sq[i] = 0.0; }
}

__global__ void count_kernel(const int* __restrict__ ei, const float* __restrict__ ew) {
    int e = blockIdx.x * blockDim.x + threadIdx.x;
    if (e < EE) {
        int c = ei[EE + e];
        atomicAdd(&g_deg[c], ew[e]);
        atomicAdd(&g_count[c], 1);
    }
}

__global__ void scan1_kernel() {
    __shared__ int s[1024];
    int t = threadIdx.x;
    int i = blockIdx.x * 1024 + t;
    int v = (i < NN) ? g_count[i] : 0;
    s[t] = v;
    if (i < NN) g_dis[i] = rsqrtf(g_deg[i]);
    __syncthreads();
    #pragma unroll
    for (int off = 1; off < 1024; off <<= 1) {
        int x = (t >= off) ? s[t - off] : 0;
        __syncthreads();
        s[t] += x;
        __syncthreads();
    }
    if (i < NN) g_rowptr[i + 1] = s[t];
    if (t == 1023) g_blocksum[blockIdx.x] = s[1023];
    if (i == 0) g_rowptr[0] = 0;
}

__global__ void scan2_kernel() {
    __shared__ int s[64];
    int t = threadIdx.x;
    const int nb = (NN + 1023) / 1024;
    int v = (t < nb) ? g_blocksum[t] : 0;
    s[t] = v;
    __syncthreads();
    #pragma unroll
    for (int off = 1; off < 64; off <<= 1) {
        int x = (t >= off) ? s[t - off] : 0;
        __syncthreads();
        s[t] += x;
        __syncthreads();
    }
    g_blockoff[t] = s[t] - v;
}

__global__ void scan3_kernel() {
    int i = blockIdx.x * blockDim.x + threadIdx.x;
    if (i < NN) g_rowptr[i + 1] += g_blockoff[i / 1024];
}

__global__ void scatter_kernel(const int* __restrict__ ei, const float* __restrict__ ew) {
    int e = blockIdx.x * blockDim.x + threadIdx.x;
    if (e < EE) {
        int r = ei[e];
        int c = ei[EE + e];
        int pos = g_rowptr[c] + atomicAdd(&g_fill[c], 1);
        g_src[pos] = r;
        g_wn[pos]  = g_dis[r] * ew[e] * g_dis[c];
    }
}

// ---------------- plain matmul (L1: x @ W1) ----------------
template <int DIN, int DOUT, int TILE>
__global__ __launch_bounds__(256)
void matmul_plain_kernel(const float* __restrict__ h, const float* __restrict__ W,
                         float* __restrict__ out) {
    constexpr int CG = DOUT / 4;
    constexpr int RG = 256 / CG;
    constexpr int RPT = TILE / RG;
    extern __shared__ float smem[];
    float* sW = smem;
    float* sH = smem + DIN * DOUT;
    int t = threadIdx.x;
    int node0 = blockIdx.x * TILE;
    for (int i = t; i < DIN * DOUT / 4; i += 256)
        ((float4*)sW)[i] = ((const float4*)W)[i];
    for (int i = t; i < TILE * DIN / 4; i += 256) {
        int nn = node0 + (i * 4) / DIN;
        float4 v = make_float4(0.f, 0.f, 0.f, 0.f);
        if (nn < NN) v = ((const float4*)h)[nn * (DIN / 4) + ((i * 4) % DIN) / 4];
        ((float4*)sH)[i] = v;
    }
    __syncthreads();
    int cg = t % CG, rg = t / CG;
    float acc[RPT][4];
    #pragma unroll
    for (int r = 0; r < RPT; r++) { acc[r][0]=0.f; acc[r][1]=0.f; acc[r][2]=0.f; acc[r][3]=0.f; }
    const float* sHr = sH + rg * RPT * DIN;
    #pragma unroll 8
    for (int k = 0; k < DIN; k++) {
        float4 wv = *(const float4*)(sW + k * DOUT + cg * 4);
        #pragma unroll
        for (int r = 0; r < RPT; r++) {
            float hv = sHr[r * DIN + k];
            acc[r][0] += hv * wv.x; acc[r][1] += hv * wv.y;
            acc[r][2] += hv * wv.z; acc[r][3] += hv * wv.w;
        }
    }
    #pragma unroll
    for (int r = 0; r < RPT; r++) {
        int node = node0 + rg * RPT + r;
        if (node < NN)
            ((float4*)out)[node * (DOUT / 4) + cg] =
                make_float4(acc[r][0], acc[r][1], acc[r][2], acc[r][3]);
    }
}

// ---------------- matmul + bias (+relu) + BN-stats epilogue ----------------
template <int DIN, int DOUT, bool RELU, int TILE>
__global__ __launch_bounds__(256)
void matmul_epi_kernel(const float* __restrict__ agg, const float* __restrict__ W,
                       const float* __restrict__ bias, float* __restrict__ out,
                       int stat_off) {
    constexpr int CG = DOUT / 4;
    constexpr int RG = 256 / CG;
    constexpr int RPT = TILE / RG;
    extern __shared__ float smem[];
    float* sW = smem;
    float* sH = smem + DIN * DOUT;
    __shared__ float s_sum[DOUT], s_sq[DOUT];
    int t = threadIdx.x;
    for (int i = t; i < DOUT; i += 256) { s_sum[i] = 0.f; s_sq[i] = 0.f; }
    int node0 = blockIdx.x * TILE;
    for (int i = t; i < DIN * DOUT / 4; i += 256)
        ((float4*)sW)[i] = ((const float4*)W)[i];
    for (int i = t; i < TILE * DIN / 4; i += 256) {
        int nn = node0 + (i * 4) / DIN;
        float4 v = make_float4(0.f, 0.f, 0.f, 0.f);
        if (nn < NN) v = ((const float4*)agg)[nn * (DIN / 4) + ((i * 4) % DIN) / 4];
        ((float4*)sH)[i] = v;
    }
    __syncthreads();
    int cg = t % CG, rg = t / CG;
    float acc[RPT][4];
    #pragma unroll
    for (int r = 0; r < RPT; r++) { acc[r][0]=0.f; acc[r][1]=0.f; acc[r][2]=0.f; acc[r][3]=0.f; }
    const float* sHr = sH + rg * RPT * DIN;
    #pragma unroll 8
    for (int k = 0; k < DIN; k++) {
        float4 wv = *(const float4*)(sW + k * DOUT + cg * 4);
        #pragma unroll
        for (int r = 0; r < RPT; r++) {
            float hv = sHr[r * DIN + k];
            acc[r][0] += hv * wv.x; acc[r][1] += hv * wv.y;
            acc[r][2] += hv * wv.z; acc[r][3] += hv * wv.w;
        }
    }
    float b0 = bias[cg * 4 + 0], b1 = bias[cg * 4 + 1];
    float b2 = bias[cg * 4 + 2], b3 = bias[cg * 4 + 3];
    float ls0 = 0.f, ls1 = 0.f, ls2 = 0.f, ls3 = 0.f;
    float lq0 = 0.f, lq1 = 0.f, lq2 = 0.f, lq3 = 0.f;
    #pragma unroll
    for (int r = 0; r < RPT; r++) {
        int node = node0 + rg * RPT + r;
        if (node < NN) {
            float v0 = acc[r][0] + b0, v1 = acc[r][1] + b1;
            float v2 = acc[r][2] + b2, v3 = acc[r][3] + b3;
            if (RELU) {
                v0 = fmaxf(v0, 0.f); v1 = fmaxf(v1, 0.f);
                v2 = fmaxf(v2, 0.f); v3 = fmaxf(v3, 0.f);
            }
            ((float4*)out)[node * CG + cg] = make_float4(v0, v1, v2, v3);
            ls0 += v0; lq0 += v0 * v0;
            ls1 += v1; lq1 += v1 * v1;
            ls2 += v2; lq2 += v2 * v2;
            ls3 += v3; lq3 += v3 * v3;
        }
    }
    atomicAdd(&s_sum[cg * 4 + 0], ls0); atomicAdd(&s_sq[cg * 4 + 0], lq0);
    atomicAdd(&s_sum[cg * 4 + 1], ls1); atomicAdd(&s_sq[cg * 4 + 1], lq1);
    atomicAdd(&s_sum[cg * 4 + 2], ls2); atomicAdd(&s_sq[cg * 4 + 2], lq2);
    atomicAdd(&s_sum[cg * 4 + 3], ls3); atomicAdd(&s_sq[cg * 4 + 3], lq3);
    __syncthreads();
    for (int i = t; i < DOUT; i += 256) {
        atomicAdd(&g_sum[stat_off + i], (double)s_sum[i]);
        atomicAdd(&g_sq[stat_off + i],  (double)s_sq[i]);
    }
}

// ---------------- L1 aggregate (post-matmul) + bias + relu + stats ----------------
template <int DOUT, bool RELU>
__global__ __launch_bounds__(256)
void aggregate_post_kernel(const float* __restrict__ m, const float* __restrict__ b,
                           float* __restrict__ out, int stat_off) {
    constexpr int NT  = DOUT / 4;
    constexpr int NPB = 256 / NT;
    __shared__ float s_sum[DOUT], s_sq[DOUT];
    int tid = threadIdx.x;
    for (int i = tid; i < DOUT; i += 256) { s_sum[i] = 0.f; s_sq[i] = 0.f; }
    __syncthreads();
    int lane = tid % NT;
    int node = blockIdx.x * NPB + tid / NT;
    const float4* m4 = (const float4*)m;
    if (node < NN) {
        float dn = g_dis[node];
        float sn = dn * dn;
        float a0 = b[lane * 4 + 0], a1 = b[lane * 4 + 1];
        float a2 = b[lane * 4 + 2], a3 = b[lane * 4 + 3];
        float4 mv = __ldg(m4 + node * NT + lane);
        a0 += sn * mv.x; a1 += sn * mv.y; a2 += sn * mv.z; a3 += sn * mv.w;
        int e0 = g_rowptr[node], e1 = g_rowptr[node + 1];
        for (int e = e0; e < e1; e++) {
            int   s = __ldg(&g_src[e]);
            float w = __ldg(&g_wn[e]);
            float4 v = __ldg(m4 + s * NT + lane);
            a0 += w * v.x; a1 += w * v.y; a2 += w * v.z; a3 += w * v.w;
        }
        if (RELU) {
            a0 = fmaxf(a0, 0.f); a1 = fmaxf(a1, 0.f);
            a2 = fmaxf(a2, 0.f); a3 = fmaxf(a3, 0.f);
        }
        ((float4*)out)[node * NT + lane] = make_float4(a0, a1, a2, a3);
        atomicAdd(&s_sum[lane * 4 + 0], a0); atomicAdd(&s_sq[lane * 4 + 0], a0 * a0);
        atomicAdd(&s_sum[lane * 4 + 1], a1); atomicAdd(&s_sq[lane * 4 + 1], a1 * a1);
        atomicAdd(&s_sum[lane * 4 + 2], a2); atomicAdd(&s_sq[lane * 4 + 2], a2 * a2);
        atomicAdd(&s_sum[lane * 4 + 3], a3); atomicAdd(&s_sq[lane * 4 + 3], a3 * a3);
    }
    __syncthreads();
    for (int i = tid; i < DOUT; i += 256) {
        atomicAdd(&g_sum[stat_off + i], (double)s_sum[i]);
        atomicAdd(&g_sq[stat_off + i],  (double)s_sq[i]);
    }
}

// ---------------- pre-aggregate with BN fused (input side) ----------------
// RELU=false: agg(s*v+sh) = s*agg(v) + sh*wsum  (BN folded out of inner loop)
// RELU=true : per-element relu(s*v+sh), gathered (L5 input = relu(bn(conv4)))
template <int DIN, bool RELU>
__global__ __launch_bounds__(256)
void preagg_kernel(const float* __restrict__ h, float* __restrict__ out,
                   const float* __restrict__ gamma, const float* __restrict__ beta,
                   int stat_off) {
    constexpr int NT  = DIN / 4;
    constexpr int NPB = 256 / NT;
    __shared__ float sS[DIN], sF[DIN];
    int t = threadIdx.x;
    if (t < DIN) {
        double mu  = g_sum[stat_off + t] / (double)NN;
        double var = g_sq[stat_off + t] / (double)NN - mu * mu;
        if (var < 0.0) var = 0.0;
        double sc = (double)gamma[t] * rsqrt(var + 1e-5);
        sS[t] = (float)sc;
        sF[t] = (float)((double)beta[t] - mu * sc);
    }
    __syncthreads();
    int lane = t % NT;
    int node = blockIdx.x * NPB + t / NT;
    if (node >= NN) return;
    const float4* h4 = (const float4*)h;
    float s0 = sS[lane * 4 + 0], s1 = sS[lane * 4 + 1];
    float s2 = sS[lane * 4 + 2], s3 = sS[lane * 4 + 3];
    float f0 = sF[lane * 4 + 0], f1 = sF[lane * 4 + 1];
    float f2 = sF[lane * 4 + 2], f3 = sF[lane * 4 + 3];
    float dn = g_dis[node];
    float sn = dn * dn;
    float a0, a1, a2, a3;
    float wsum = sn;
    {
        float4 v = __ldg(h4 + node * NT + lane);
        if (RELU) {
            a0 = sn * fmaxf(s0 * v.x + f0, 0.f);
            a1 = sn * fmaxf(s1 * v.y + f1, 0.f);
            a2 = sn * fmaxf(s2 * v.z + f2, 0.f);
            a3 = sn * fmaxf(s3 * v.w + f3, 0.f);
        } else {
            a0 = sn * v.x; a1 = sn * v.y; a2 = sn * v.z; a3 = sn * v.w;
        }
    }
    int e0 = g_rowptr[node], e1 = g_rowptr[node + 1];
    for (int e = e0; e < e1; e++) {
        int   s = __ldg(&g_src[e]);
        float w = __ldg(&g_wn[e]);
        float4 v = __ldg(h4 + s * NT + lane);
        if (RELU) {
            a0 += w * fmaxf(s0 * v.x + f0, 0.f);
            a1 += w * fmaxf(s1 * v.y + f1, 0.f);
            a2 += w * fmaxf(s2 * v.z + f2, 0.f);
            a3 += w * fmaxf(s3 * v.w + f3, 0.f);
        } else {
            a0 += w * v.x; a1 += w * v.y; a2 += w * v.z; a3 += w * v.w;
            wsum += w;
        }
    }
    if (!RELU) {
        a0 = s0 * a0 + f0 * wsum;
        a1 = s1 * a1 + f1 * wsum;
        a2 = s2 * a2 + f2 * wsum;
        a3 = s3 * a3 + f3 * wsum;
    }
    ((float4*)out)[node * NT + lane] = make_float4(a0, a1, a2, a3);
}

// ---------------- layer5 BN + global_add_pool ----------------
__global__ __launch_bounds__(256)
void pool_kernel(const float* __restrict__ h, const int* __restrict__ batch,
                 const float* __restrict__ gamma, const float* __restrict__ beta) {
    __shared__ float sScale[128], sShift[128];
    int t = threadIdx.x;
    if (t < 128) {
        double mu  = g_sum[512 + t] / (double)NN;
        double var = g_sq[512 + t] / (double)NN - mu * mu;
        if (var < 0.0) var = 0.0;
        double sc = (double)gamma[t] * rsqrt(var + 1e-5);
        sScale[t] = (float)sc;
        sShift[t] = (float)((double)beta[t] - mu * sc);
    }
    __syncthreads();
    constexpr int NODES = 64;
    int lane = t % 32;
    int grp  = t / 32;
    int base = blockIdx.x * NODES;
    float a0 = 0.f, a1 = 0.f, a2 = 0.f, a3 = 0.f;
    int cur = -1;
    float s0 = sScale[lane * 4 + 0], s1 = sScale[lane * 4 + 1];
    float s2 = sScale[lane * 4 + 2], s3 = sScale[lane * 4 + 3];
    float h0 = sShift[lane * 4 + 0], h1 = sShift[lane * 4 + 1];
    float h2 = sShift[lane * 4 + 2], h3 = sShift[lane * 4 + 3];
    for (int n = grp; n < NODES; n += 8) {
        int node = base + n;
        if (node >= NN) break;
        int bidx = batch[node];
        if (bidx != cur) {
            if (cur >= 0) {
                atomicAdd(&g_pooled[cur * 128 + lane * 4 + 0], a0);
                atomicAdd(&g_pooled[cur * 128 + lane * 4 + 1], a1);
                atomicAdd(&g_pooled[cur * 128 + lane * 4 + 2], a2);
                atomicAdd(&g_pooled[cur * 128 + lane * 4 + 3], a3);
            }
            cur = bidx; a0 = a1 = a2 = a3 = 0.f;
        }
        float4 v = ((const float4*)h)[node * 32 + lane];
        a0 += s0 * v.x + h0;
        a1 += s1 * v.y + h1;
        a2 += s2 * v.z + h2;
        a3 += s3 * v.w + h3;
    }
    if (cur >= 0) {
        atomicAdd(&g_pooled[cur * 128 + lane * 4 + 0], a0);
        atomicAdd(&g_pooled[cur * 128 + lane * 4 + 1], a1);
        atomicAdd(&g_pooled[cur * 128 + lane * 4 + 2], a2);
        atomicAdd(&g_pooled[cur * 128 + lane * 4 + 3], a3);
    }
}

// ---------------- final MLP ----------------
__global__ void mlp_kernel(const float* __restrict__ fc1_w, const float* __restrict__ fc1_b,
                           const float* __restrict__ fc2_w, const float* __restrict__ fc2_b,
                           float* __restrict__ out) {
    int g = blockIdx.x;
    int t = threadIdx.x;  // 64
    __shared__ float sp[FMAX];
    for (int i = t; i < FMAX; i += 64) sp[i] = fmaxf(g_pooled[g * FMAX + i], 0.0f);
    __syncthreads();
    float acc = fc1_b[t];
    #pragma unroll 4
    for (int k = 0; k < FMAX; k++) acc += sp[k] * fc1_w[k * 64 + t];
    acc = fmaxf(acc, 0.0f);
    float v = acc * fc2_w[t];
    #pragma unroll
    for (int off = 16; off > 0; off >>= 1) v += __shfl_down_sync(0xffffffffu, v, off);
    __shared__ float red[2];
    if ((t & 31) == 0) red[t >> 5] = v;
    __syncthreads();
    if (t == 0) out[g] = red[0] + red[1] + fc2_b[0];
}

// ---------------- launch ----------------
extern "C" void kernel_launch(void* const* d_in, const int* in_sizes, int n_in,
                              void* d_out, int out_size) {
    const float* x     = (const float*)d_in[0];
    const int*   ei    = (const int*)d_in[1];
    const float* ew    = (const float*)d_in[2];
    const int*   batch = (const int*)d_in[3];
    const float *W1 = (const float*)d_in[4],  *b1 = (const float*)d_in[5],
                *g1 = (const float*)d_in[6],  *bt1 = (const float*)d_in[7];
    const float *W2 = (const float*)d_in[8],  *b2 = (const float*)d_in[9],
                *g2 = (const float*)d_in[10], *bt2 = (const float*)d_in[11];
    const float *W3 = (const float*)d_in[12], *b3 = (const float*)d_in[13],
                *g3 = (const float*)d_in[14], *bt3 = (const float*)d_in[15];
    const float *W4 = (const float*)d_in[16], *b4 = (const float*)d_in[17],
                *g4 = (const float*)d_in[18], *bt4 = (const float*)d_in[19];
    const float *W5 = (const float*)d_in[20], *b5 = (const float*)d_in[21],
                *g5 = (const float*)d_in[22], *bt5 = (const float*)d_in[23];
    const float* fc1_w = (const float*)d_in[24];
    const float* fc1_b = (const float*)d_in[25];
    const float* fc2_w = (const float*)d_in[26];
    const float* fc2_b = (const float*)d_in[27];
    float* out = (float*)d_out;

    float *bufA, *bufB, *bufM;
    cudaGetSymbolAddress((void**)&bufA, g_bufA);
    cudaGetSymbolAddress((void**)&bufB, g_bufB);
    cudaGetSymbolAddress((void**)&bufM, g_m);

    const int TB = 256;
    init_kernel<<<(NN + TB - 1) / TB, TB>>>();
    count_kernel<<<(EE + TB - 1) / TB, TB>>>(ei, ew);
    scan1_kernel<<<(NN + 1023) / 1024, 1024>>>();
    scan2_kernel<<<1, 64>>>();
    scan3_kernel<<<(NN + TB - 1) / TB, TB>>>();
    scatter_kernel<<<(EE + TB - 1) / TB, TB>>>(ei, ew);

    auto smem = [](int din, int dout, int tile) {
        return (din * dout + tile * din) * 4;
    };

    // L1 (128->16): matmul then aggregate(bias,relu,stats@0) -> h1_raw
    matmul_plain_kernel<128, 16, 64><<<(NN + 63) / 64, 256, smem(128, 16, 64)>>>(x, W1, bufM);
    aggregate_post_kernel<16, true><<<(NN * 4 + 255) / 256, 256>>>(bufM, b1, bufA, 0);

    // L2 (16->32): preagg(bn1) -> matmul+b2+relu+stats@128 -> h2_raw
    preagg_kernel<16, false><<<(NN * 4 + 255) / 256, 256>>>(bufA, bufB, g1, bt1, 0);
    matmul_epi_kernel<16, 32, true, 64><<<(NN + 63) / 64, 256, smem(16, 32, 64)>>>(
        bufB, W2, b2, bufA, 128);

    // L3 (32->64): preagg(bn2) -> matmul+b3+relu+stats@256 -> h3_raw
    preagg_kernel<32, false><<<(NN * 8 + 255) / 256, 256>>>(bufA, bufB, g2, bt2, 128);
    matmul_epi_kernel<32, 64, true, 64><<<(NN + 63) / 64, 256, smem(32, 64, 64)>>>(
        bufB, W3, b3, bufA, 256);

    // L4 (64->64): preagg(bn3) -> matmul+b4 (no relu) +stats@384 -> c4_raw
    preagg_kernel<64, false><<<(NN * 16 + 255) / 256, 256>>>(bufA, bufB, g3, bt3, 256);
    matmul_epi_kernel<64, 64, false, 64><<<(NN + 63) / 64, 256, smem(64, 64, 64)>>>(
        bufB, W4, b4, bufA, 384);

    // L5 (64->128): preagg(relu(bn4)) -> matmul+b5 (no relu) +stats@512 -> c5_raw
    preagg_kernel<64, true><<<(NN * 16 + 255) / 256, 256>>>(bufA, bufB, g4, bt4, 384);
    matmul_epi_kernel<64, 128, false, 56><<<(NN + 55) / 56, 256, smem(64, 128, 56)>>>(
        bufB, W5, b5, bufA, 512);

    // BN5 + pool, then MLP head
    pool_kernel<<<(NN + 63) / 64, 256>>>(bufA, batch, g5, bt5);
    mlp_kernel<<<GG, 64>>>(fc1_w, fc1_b, fc2_w, fc2_b, out);
}

// round 5
// speedup vs baseline: 1.9450x; 1.0074x over previous
#include <cuda_runtime.h>
#include <cuda_bf16.h>

#define NN 50000
#define EE 800000
#define GG 256
#define FMAX 128
#define NB_SCAN 49   // ceil(50000/1024)

// stat offsets: L1=0(16) L2=128(32) L3=256(64) L4=384(64) L5=512(128)
__device__ unsigned long long g_pack[NN];   // count<<42 | weightsum_fx32
__device__ float  g_dis[NN];
__device__ int    g_rowptr[NN + 1];
__device__ int    g_blocksum[64];
__device__ int    g_src[EE];
__device__ float  g_wn[EE];
__device__ float  g_bufA[NN * FMAX];   // h1(16) / h3(64) / c5(128)
__device__ float  g_bufB[NN * 64];     // h2(32) / c4(64)
__device__ float  g_m[NN * 16];        // L1 matmul output
__device__ double g_sum[640];
__device__ double g_sq[640];
__device__ float  g_pooled[GG * FMAX];

// ---------------- preprocessing ----------------
__global__ void init_kernel() {
    int i = blockIdx.x * blockDim.x + threadIdx.x;
    if (i < NN) g_pack[i] = 0ULL;
    if (i < GG * FMAX) g_pooled[i] = 0.0f;
    if (i < 640) { g_sum[i] = 0.0; g_sq[i] = 0.0; }
}

__global__ void count_kernel(const int* __restrict__ ei, const float* __restrict__ ew) {
    int e = blockIdx.x * blockDim.x + threadIdx.x;
    if (e < EE) {
        int c = ei[EE + e];
        unsigned long long p = (1ULL << 42) |
            (unsigned long long)(ew[e] * 4294967296.0f);
        atomicAdd(&g_pack[c], p);
    }
}

// block-local scan; writes LOCAL exclusive starts + dis
__global__ void scan1_kernel() {
    __shared__ int s[1024];
    int t = threadIdx.x;
    int i = blockIdx.x * 1024 + t;
    unsigned long long p = (i < NN) ? g_pack[i] : 0ULL;
    int v = (int)(p >> 42);
    s[t] = v;
    if (i < NN) {
        double wfx = (double)(p & ((1ULL << 42) - 1ULL)) * 2.3283064365386963e-10;
        g_dis[i] = rsqrtf((float)(1.0 + wfx));
    }
    __syncthreads();
    #pragma unroll
    for (int off = 1; off < 1024; off <<= 1) {
        int x = (t >= off) ? s[t - off] : 0;
        __syncthreads();
        s[t] += x;
        __syncthreads();
    }
    if (i < NN) g_rowptr[i] = s[t] - v;   // local exclusive start
    if (t == 1023) g_blocksum[blockIdx.x] = s[1023];
}

// each block recomputes the 49-entry exclusive scan, adds its offset
__global__ void scanfix_kernel() {
    __shared__ int so[64];
    int t = threadIdx.x;
    if (t < 64) so[t] = (t >= 1 && t - 1 < NB_SCAN) ? g_blocksum[t - 1] : 0;
    __syncthreads();
    #pragma unroll
    for (int off = 1; off < 64; off <<= 1) {
        int x = (t < 64 && t >= off) ? so[t - off] : 0;
        __syncthreads();
        if (t < 64) so[t] += x;
        __syncthreads();
    }
    int add = so[blockIdx.x];
    int i = blockIdx.x * 1024 + t;
    if (i < NN) g_rowptr[i] += add;
}

// scatter; rowptr[c] doubles as fill cursor (post: rowptr[i] = end of node i)
__global__ void scatter_kernel(const int* __restrict__ ei, const float* __restrict__ ew) {
    int e = blockIdx.x * blockDim.x + threadIdx.x;
    if (e < EE) {
        int r = ei[e];
        int c = ei[EE + e];
        int pos = atomicAdd(&g_rowptr[c], 1);
        g_src[pos] = r;
        g_wn[pos]  = g_dis[r] * ew[e] * g_dis[c];
    }
}

// ---------------- L1 matmul: m = x @ W1 ----------------
template <int DIN, int DOUT, int TILE>
__global__ __launch_bounds__(256)
void matmul_plain_kernel(const float* __restrict__ h, const float* __restrict__ W,
                         float* __restrict__ out) {
    constexpr int CG = DOUT / 4;
    constexpr int RG = 256 / CG;
    constexpr int RPT = TILE / RG;
    extern __shared__ float smem[];
    float* sW = smem;
    float* sH = smem + DIN * DOUT;
    int t = threadIdx.x;
    int node0 = blockIdx.x * TILE;
    for (int i = t; i < DIN * DOUT / 4; i += 256)
        ((float4*)sW)[i] = ((const float4*)W)[i];
    for (int i = t; i < TILE * DIN / 4; i += 256) {
        int nn = node0 + (i * 4) / DIN;
        float4 v = make_float4(0.f, 0.f, 0.f, 0.f);
        if (nn < NN) v = ((const float4*)h)[nn * (DIN / 4) + ((i * 4) % DIN) / 4];
        ((float4*)sH)[i] = v;
    }
    __syncthreads();
    int cg = t % CG, rg = t / CG;
    float acc[RPT][4];
    #pragma unroll
    for (int r = 0; r < RPT; r++) { acc[r][0]=0.f; acc[r][1]=0.f; acc[r][2]=0.f; acc[r][3]=0.f; }
    const float* sHr = sH + rg * RPT * DIN;
    #pragma unroll 8
    for (int k = 0; k < DIN; k++) {
        float4 wv = *(const float4*)(sW + k * DOUT + cg * 4);
        #pragma unroll
        for (int r = 0; r < RPT; r++) {
            float hv = sHr[r * DIN + k];
            acc[r][0] += hv * wv.x; acc[r][1] += hv * wv.y;
            acc[r][2] += hv * wv.z; acc[r][3] += hv * wv.w;
        }
    }
    #pragma unroll
    for (int r = 0; r < RPT; r++) {
        int node = node0 + rg * RPT + r;
        if (node < NN)
            ((float4*)out)[node * (DOUT / 4) + cg] =
                make_float4(acc[r][0], acc[r][1], acc[r][2], acc[r][3]);
    }
}

// ---------------- L1 aggregate + bias + relu + stats ----------------
template <int DOUT>
__global__ __launch_bounds__(256)
void aggregate_post_kernel(const float* __restrict__ m, const float* __restrict__ b,
                           float* __restrict__ out, int stat_off) {
    constexpr int NT  = DOUT / 4;
    constexpr int NPB = 256 / NT;
    __shared__ float s_sum[DOUT], s_sq[DOUT];
    int tid = threadIdx.x;
    for (int i = tid; i < DOUT; i += 256) { s_sum[i] = 0.f; s_sq[i] = 0.f; }
    __syncthreads();
    int lane = tid % NT;
    int node = blockIdx.x * NPB + tid / NT;
    const float4* m4 = (const float4*)m;
    if (node < NN) {
        float dn = g_dis[node];
        float sn = dn * dn;
        float a0 = b[lane*4+0], a1 = b[lane*4+1], a2 = b[lane*4+2], a3 = b[lane*4+3];
        float4 mv = __ldg(m4 + node * NT + lane);
        a0 += sn * mv.x; a1 += sn * mv.y; a2 += sn * mv.z; a3 += sn * mv.w;
        int e0 = node ? g_rowptr[node - 1] : 0;
        int e1 = g_rowptr[node];
        int e = e0;
        for (; e + 2 <= e1; e += 2) {
            int   sA = __ldg(&g_src[e]);     float wA = __ldg(&g_wn[e]);
            int   sB = __ldg(&g_src[e + 1]); float wB = __ldg(&g_wn[e + 1]);
            float4 vA = __ldg(m4 + sA * NT + lane);
            float4 vB = __ldg(m4 + sB * NT + lane);
            a0 += wA * vA.x; a1 += wA * vA.y; a2 += wA * vA.z; a3 += wA * vA.w;
            a0 += wB * vB.x; a1 += wB * vB.y; a2 += wB * vB.z; a3 += wB * vB.w;
        }
        if (e < e1) {
            int   s = __ldg(&g_src[e]);
            float w = __ldg(&g_wn[e]);
            float4 v = __ldg(m4 + s * NT + lane);
            a0 += w * v.x; a1 += w * v.y; a2 += w * v.z; a3 += w * v.w;
        }
        a0 = fmaxf(a0, 0.f); a1 = fmaxf(a1, 0.f);
        a2 = fmaxf(a2, 0.f); a3 = fmaxf(a3, 0.f);
        ((float4*)out)[node * NT + lane] = make_float4(a0, a1, a2, a3);
        atomicAdd(&s_sum[lane*4+0], a0); atomicAdd(&s_sq[lane*4+0], a0*a0);
        atomicAdd(&s_sum[lane*4+1], a1); atomicAdd(&s_sq[lane*4+1], a1*a1);
        atomicAdd(&s_sum[lane*4+2], a2); atomicAdd(&s_sq[lane*4+2], a2*a2);
        atomicAdd(&s_sum[lane*4+3], a3); atomicAdd(&s_sq[lane*4+3], a3*a3);
    }
    __syncthreads();
    for (int i = tid; i < DOUT; i += 256) {
        atomicAdd(&g_sum[stat_off + i], (double)s_sum[i]);
        atomicAdd(&g_sq[stat_off + i],  (double)s_sq[i]);
    }
}

// ---------------- fused: gather(BN-in) -> matmul -> bias(+relu) + stats ----------------
// MODE_IN 0: bn folded out of loop (a = s*agg + f*wsum); 1: relu(bn) per element.
template <int DIN, int DOUT, int MODE_IN, bool RELU_OUT, int TILE, int TPN>
__global__ __launch_bounds__(512)
void fused_layer_kernel(const float* __restrict__ h, const float* __restrict__ W,
                        const float* __restrict__ bias, float* __restrict__ out,
                        const float* __restrict__ gamma, const float* __restrict__ beta,
                        int stat_in, int stat_out) {
    constexpr int CG  = DOUT / 4;
    constexpr int RG  = 512 / CG;
    constexpr int RPT = TILE / RG;
    constexpr int F4  = DIN / 4 / TPN;   // float4 slots per gather thread
    extern __shared__ float smem[];
    float* sW = smem;                 // DIN*DOUT
    float* sH = smem + DIN * DOUT;    // TILE*DIN
    __shared__ float sS[DIN], sF[DIN];
    __shared__ float s_sum[DOUT], s_sq[DOUT];
    int t = threadIdx.x;
    if (t < DIN) {
        double mu  = g_sum[stat_in + t] / (double)NN;
        double var = g_sq[stat_in + t] / (double)NN - mu * mu;
        if (var < 0.0) var = 0.0;
        double sc = (double)gamma[t] * rsqrt(var + 1e-5);
        sS[t] = (float)sc;
        sF[t] = (float)((double)beta[t] - mu * sc);
    }
    for (int i = t; i < DOUT; i += 512) { s_sum[i] = 0.f; s_sq[i] = 0.f; }
    for (int i = t; i < DIN * DOUT / 4; i += 512)
        ((float4*)sW)[i] = ((const float4*)W)[i];
    __syncthreads();

    int node0 = blockIdx.x * TILE;
    // ---- gather phase ----
    if (t < TILE * TPN) {
        int local = t / TPN;
        int sub   = t % TPN;
        int base  = sub * F4;
        int node  = node0 + local;
        float a[F4][4];
        #pragma unroll
        for (int j = 0; j < F4; j++) { a[j][0]=0.f; a[j][1]=0.f; a[j][2]=0.f; a[j][3]=0.f; }
        if (node < NN) {
            const float4* h4 = (const float4*)h;
            float rs[F4][4], rf[F4][4];
            if (MODE_IN == 1) {
                #pragma unroll
                for (int j = 0; j < F4; j++) {
                    int c = (base + j) * 4;
                    rs[j][0]=sS[c]; rs[j][1]=sS[c+1]; rs[j][2]=sS[c+2]; rs[j][3]=sS[c+3];
                    rf[j][0]=sF[c]; rf[j][1]=sF[c+1]; rf[j][2]=sF[c+2]; rf[j][3]=sF[c+3];
                }
            }
            auto acc1 = [&](int s, float w) {
                #pragma unroll
                for (int j = 0; j < F4; j++) {
                    float4 v = __ldg(h4 + s * (DIN / 4) + base + j);
                    if (MODE_IN == 1) {
                        a[j][0] += w * fmaxf(rs[j][0]*v.x + rf[j][0], 0.f);
                        a[j][1] += w * fmaxf(rs[j][1]*v.y + rf[j][1], 0.f);
                        a[j][2] += w * fmaxf(rs[j][2]*v.z + rf[j][2], 0.f);
                        a[j][3] += w * fmaxf(rs[j][3]*v.w + rf[j][3], 0.f);
                    } else {
                        a[j][0] += w*v.x; a[j][1] += w*v.y; a[j][2] += w*v.z; a[j][3] += w*v.w;
                    }
                }
            };
            float dn = g_dis[node];
            float sn = dn * dn;
            float wsum = sn;
            acc1(node, sn);
            int e0 = node ? g_rowptr[node - 1] : 0;
            int e1 = g_rowptr[node];
            int e = e0;
            for (; e + 2 <= e1; e += 2) {
                int   sA = __ldg(&g_src[e]);     float wA = __ldg(&g_wn[e]);
                int   sB = __ldg(&g_src[e + 1]); float wB = __ldg(&g_wn[e + 1]);
                float4 vA[F4], vB[F4];
                #pragma unroll
                for (int j = 0; j < F4; j++) vA[j] = __ldg(h4 + sA * (DIN/4) + base + j);
                #pragma unroll
                for (int j = 0; j < F4; j++) vB[j] = __ldg(h4 + sB * (DIN/4) + base + j);
                #pragma unroll
                for (int j = 0; j < F4; j++) {
                    if (MODE_IN == 1) {
                        a[j][0] += wA * fmaxf(rs[j][0]*vA[j].x + rf[j][0], 0.f)
                                 + wB * fmaxf(rs[j][0]*vB[j].x + rf[j][0], 0.f);
                        a[j][1] += wA * fmaxf(rs[j][1]*vA[j].y + rf[j][1], 0.f)
                                 + wB * fmaxf(rs[j][1]*vB[j].y + rf[j][1], 0.f);
                        a[j][2] += wA * fmaxf(rs[j][2]*vA[j].z + rf[j][2], 0.f)
                                 + wB * fmaxf(rs[j][2]*vB[j].z + rf[j][2], 0.f);
                        a[j][3] += wA * fmaxf(rs[j][3]*vA[j].w + rf[j][3], 0.f)
                                 + wB * fmaxf(rs[j][3]*vB[j].w + rf[j][3], 0.f);
                    } else {
                        a[j][0] += wA*vA[j].x + wB*vB[j].x;
                        a[j][1] += wA*vA[j].y + wB*vB[j].y;
                        a[j][2] += wA*vA[j].z + wB*vB[j].z;
                        a[j][3] += wA*vA[j].w + wB*vB[j].w;
                    }
                }
                wsum += wA + wB;
            }
            if (e < e1) {
                int   s = __ldg(&g_src[e]);
                float w = __ldg(&g_wn[e]);
                acc1(s, w);
                wsum += w;
            }
            if (MODE_IN == 0) {
                #pragma unroll
                for (int j = 0; j < F4; j++) {
                    int c = (base + j) * 4;
                    a[j][0] = sS[c+0]*a[j][0] + sF[c+0]*wsum;
                    a[j][1] = sS[c+1]*a[j][1] + sF[c+1]*wsum;
                    a[j][2] = sS[c+2]*a[j][2] + sF[c+2]*wsum;
                    a[j][3] = sS[c+3]*a[j][3] + sF[c+3]*wsum;
                }
            }
        }
        #pragma unroll
        for (int j = 0; j < F4; j++)
            ((float4*)sH)[local * (DIN / 4) + base + j] =
                make_float4(a[j][0], a[j][1], a[j][2], a[j][3]);
    }
    __syncthreads();

    // ---- matmul phase ----
    int cg = t % CG, rg = t / CG;
    float acc[RPT][4];
    #pragma unroll
    for (int r = 0; r < RPT; r++) { acc[r][0]=0.f; acc[r][1]=0.f; acc[r][2]=0.f; acc[r][3]=0.f; }
    const float* sHr = sH + rg * RPT * DIN;
    #pragma unroll 8
    for (int k = 0; k < DIN; k++) {
        float4 wv = *(const float4*)(sW + k * DOUT + cg * 4);
        #pragma unroll
        for (int r = 0; r < RPT; r++) {
            float hv = sHr[r * DIN + k];
            acc[r][0] += hv * wv.x; acc[r][1] += hv * wv.y;
            acc[r][2] += hv * wv.z; acc[r][3] += hv * wv.w;
        }
    }
    float b0 = bias[cg*4+0], b1 = bias[cg*4+1], b2 = bias[cg*4+2], b3 = bias[cg*4+3];
    float ls0=0.f, ls1=0.f, ls2=0.f, ls3=0.f, lq0=0.f, lq1=0.f, lq2=0.f, lq3=0.f;
    #pragma unroll
    for (int r = 0; r < RPT; r++) {
        int node = node0 + rg * RPT + r;
        if (node < NN) {
            float v0 = acc[r][0] + b0, v1 = acc[r][1] + b1;
            float v2 = acc[r][2] + b2, v3 = acc[r][3] + b3;
            if (RELU_OUT) {
                v0 = fmaxf(v0, 0.f); v1 = fmaxf(v1, 0.f);
                v2 = fmaxf(v2, 0.f); v3 = fmaxf(v3, 0.f);
            }
            ((float4*)out)[node * CG + cg] = make_float4(v0, v1, v2, v3);
            ls0 += v0; lq0 += v0*v0; ls1 += v1; lq1 += v1*v1;
            ls2 += v2; lq2 += v2*v2; ls3 += v3; lq3 += v3*v3;
        }
    }
    atomicAdd(&s_sum[cg*4+0], ls0); atomicAdd(&s_sq[cg*4+0], lq0);
    atomicAdd(&s_sum[cg*4+1], ls1); atomicAdd(&s_sq[cg*4+1], lq1);
    atomicAdd(&s_sum[cg*4+2], ls2); atomicAdd(&s_sq[cg*4+2], lq2);
    atomicAdd(&s_sum[cg*4+3], ls3); atomicAdd(&s_sq[cg*4+3], lq3);
    __syncthreads();
    for (int i = t; i < DOUT; i += 512) {
        atomicAdd(&g_sum[stat_out + i], (double)s_sum[i]);
        atomicAdd(&g_sq[stat_out + i],  (double)s_sq[i]);
    }
}

// ---------------- layer5 BN + global_add_pool ----------------
__global__ __launch_bounds__(256)
void pool_kernel(const float* __restrict__ h, const int* __restrict__ batch,
                 const float* __restrict__ gamma, const float* __restrict__ beta) {
    __shared__ float sScale[128], sShift[128];
    int t = threadIdx.x;
    if (t < 128) {
        double mu  = g_sum[512 + t] / (double)NN;
        double var = g_sq[512 + t] / (double)NN - mu * mu;
        if (var < 0.0) var = 0.0;
        double sc = (double)gamma[t] * rsqrt(var + 1e-5);
        sScale[t] = (float)sc;
        sShift[t] = (float)((double)beta[t] - mu * sc);
    }
    __syncthreads();
    constexpr int NODES = 64;
    int lane = t % 32;
    int grp  = t / 32;
    int base = blockIdx.x * NODES;
    float a0=0.f, a1=0.f, a2=0.f, a3=0.f;
    int cur = -1;
    float s0=sScale[lane*4+0], s1=sScale[lane*4+1], s2=sScale[lane*4+2], s3=sScale[lane*4+3];
    float h0=sShift[lane*4+0], h1=sShift[lane*4+1], h2=sShift[lane*4+2], h3=sShift[lane*4+3];
    for (int n = grp; n < NODES; n += 8) {
        int node = base + n;
        if (node >= NN) break;
        int bidx = batch[node];
        if (bidx != cur) {
            if (cur >= 0) {
                atomicAdd(&g_pooled[cur*128+lane*4+0], a0);
                atomicAdd(&g_pooled[cur*128+lane*4+1], a1);
                atomicAdd(&g_pooled[cur*128+lane*4+2], a2);
                atomicAdd(&g_pooled[cur*128+lane*4+3], a3);
            }
            cur = bidx; a0=a1=a2=a3=0.f;
        }
        float4 v = ((const float4*)h)[node * 32 + lane];
        a0 += s0*v.x + h0; a1 += s1*v.y + h1;
        a2 += s2*v.z + h2; a3 += s3*v.w + h3;
    }
    if (cur >= 0) {
        atomicAdd(&g_pooled[cur*128+lane*4+0], a0);
        atomicAdd(&g_pooled[cur*128+lane*4+1], a1);
        atomicAdd(&g_pooled[cur*128+lane*4+2], a2);
        atomicAdd(&g_pooled[cur*128+lane*4+3], a3);
    }
}

// ---------------- final MLP ----------------
__global__ void mlp_kernel(const float* __restrict__ fc1_w, const float* __restrict__ fc1_b,
                           const float* __restrict__ fc2_w, const float* __restrict__ fc2_b,
                           float* __restrict__ out) {
    int g = blockIdx.x;
    int t = threadIdx.x;  // 64
    __shared__ float sp[FMAX];
    for (int i = t; i < FMAX; i += 64) sp[i] = fmaxf(g_pooled[g * FMAX + i], 0.0f);
    __syncthreads();
    float acc = fc1_b[t];
    #pragma unroll 4
    for (int k = 0; k < FMAX; k++) acc += sp[k] * fc1_w[k * 64 + t];
    acc = fmaxf(acc, 0.0f);
    float v = acc * fc2_w[t];
    #pragma unroll
    for (int off = 16; off > 0; off >>= 1) v += __shfl_down_sync(0xffffffffu, v, off);
    __shared__ float red[2];
    if ((t & 31) == 0) red[t >> 5] = v;
    __syncthreads();
    if (t == 0) out[g] = red[0] + red[1] + fc2_b[0];
}

// ---------------- launch ----------------
extern "C" void kernel_launch(void* const* d_in, const int* in_sizes, int n_in,
                              void* d_out, int out_size) {
    const float* x     = (const float*)d_in[0];
    const int*   ei    = (const int*)d_in[1];
    const float* ew    = (const float*)d_in[2];
    const int*   batch = (const int*)d_in[3];
    const float *W1 = (const float*)d_in[4],  *b1 = (const float*)d_in[5],
                *g1 = (const float*)d_in[6],  *bt1 = (const float*)d_in[7];
    const float *W2 = (const float*)d_in[8],  *b2 = (const float*)d_in[9],
                *g2 = (const float*)d_in[10], *bt2 = (const float*)d_in[11];
    const float *W3 = (const float*)d_in[12], *b3 = (const float*)d_in[13],
                *g3 = (const float*)d_in[14], *bt3 = (const float*)d_in[15];
    const float *W4 = (const float*)d_in[16], *b4 = (const float*)d_in[17],
                *g4 = (const float*)d_in[18], *bt4 = (const float*)d_in[19];
    const float *W5 = (const float*)d_in[20], *b5 = (const float*)d_in[21],
                *g5 = (const float*)d_in[22], *bt5 = (const float*)d_in[23];
    const float* fc1_w = (const float*)d_in[24];
    const float* fc1_b = (const float*)d_in[25];
    const float* fc2_w = (const float*)d_in[26];
    const float* fc2_b = (const float*)d_in[27];
    float* out = (float*)d_out;

    float *bufA, *bufB, *bufM;
    cudaGetSymbolAddress((void**)&bufA, g_bufA);
    cudaGetSymbolAddress((void**)&bufB, g_bufB);
    cudaGetSymbolAddress((void**)&bufM, g_m);

    const int TB = 256;
    init_kernel<<<(NN + TB - 1) / TB, TB>>>();
    count_kernel<<<(EE + TB - 1) / TB, TB>>>(ei, ew);
    scan1_kernel<<<NB_SCAN, 1024>>>();
    scanfix_kernel<<<NB_SCAN, 1024>>>();
    scatter_kernel<<<(EE + TB - 1) / TB, TB>>>(ei, ew);

    auto smem = [](int din, int dout, int tile) {
        return (din * dout + tile * din) * 4;
    };

    // L1 (128->16): matmul + aggregate(bias,relu,stats@0) -> bufA(h1,16)
    matmul_plain_kernel<128, 16, 64><<<(NN + 63) / 64, 256, smem(128, 16, 64)>>>(x, W1, bufM);
    aggregate_post_kernel<16><<<(NN * 4 + 255) / 256, 256>>>(bufM, b1, bufA, 0);

    // L2 (16->32): gather(bn1 fold)+matmul+relu+stats@128 -> bufB(h2,32)
    fused_layer_kernel<16, 32, 0, true, 128, 4><<<(NN + 127) / 128, 512, smem(16, 32, 128)>>>(
        bufA, W2, b2, bufB, g1, bt1, 0, 128);
    // L3 (32->64): -> bufA(h3,64)
    fused_layer_kernel<32, 64, 0, true, 128, 4><<<(NN + 127) / 128, 512, smem(32, 64, 128)>>>(
        bufB, W3, b3, bufA, g2, bt2, 128, 256);
    // L4 (64->64): no relu-out -> bufB(c4,64)
    fused_layer_kernel<64, 64, 0, false, 64, 8><<<(NN + 63) / 64, 512, smem(64, 64, 64)>>>(
        bufA, W4, b4, bufB, g3, bt3, 256, 384);
    // L5 (64->128): gather relu(bn4) per element -> bufA(c5,128)
    fused_layer_kernel<64, 128, 1, false, 48, 8><<<(NN + 47) / 48, 512, smem(64, 128, 48)>>>(
        bufB, W5, b5, bufA, g4, bt4, 384, 512);

    // BN5 + pool, then MLP head
    pool_kernel<<<(NN + 63) / 64, 256>>>(bufA, batch, g5, bt5);
    mlp_kernel<<<GG, 64>>>(fc1_w, fc1_b, fc2_w, fc2_b, out);
}